// round 1
// baseline (speedup 1.0000x reference)
#include <cuda_runtime.h>

#define NB      16384
#define OWN_D   7
#define INTR_D  5
#define NH      3
#define HD      5
#define NI      256
#define HID     256
#define IN_DIM  (OWN_D + NH*HD)        // 22
#define OBS_D   (OWN_D + NI*INTR_D)    // 1287

// scratch for x1 = leaky(x @ W1 + b1)   (16 MB, static device array: allowed)
__device__ float g_x1[NB * HID];

__device__ __forceinline__ float fast_tanh(float x) {
    // 1 - 2/(e^{2x}+1): ~1e-7 abs error, saturates correctly at +-inf
    float e = __expf(2.0f * x);
    return 1.0f - __fdividef(2.0f, e + 1.0f);
}

// ---------------------------------------------------------------------------
// Kernel A: additive attention + layer 1.   1 warp per batch row, 4 warps/CTA.
// ---------------------------------------------------------------------------
__global__ void __launch_bounds__(128, 1) attn_l1_kernel(
    const float* __restrict__ obs,
    const float* __restrict__ Wq, const float* __restrict__ bq,
    const float* __restrict__ Wk, const float* __restrict__ bk,
    const float* __restrict__ Wv, const float* __restrict__ bv,
    const float* __restrict__ v_att, const float* __restrict__ temperature,
    const float* __restrict__ W1, const float* __restrict__ b1)
{
    __shared__ float sWq[NH*HD*OWN_D];             // 105
    __shared__ float sWk[NH*HD*INTR_D];            // 75
    __shared__ float sWv[NH*HD*INTR_D];            // 75
    __shared__ float sbq[NH*HD], sbk[NH*HD], sbv[NH*HD], sva[NH*HD];
    __shared__ float sW1[IN_DIM*HID];              // 5632
    __shared__ float sb1[HID];
    __shared__ float sIntr[4][NI*INTR_D];          // 4 * 1280
    __shared__ float sOwn[4][OWN_D];
    __shared__ float sX[4][IN_DIM];

    const int tid = threadIdx.x;
    for (int i = tid; i < NH*HD*OWN_D;  i += 128) sWq[i] = Wq[i];
    for (int i = tid; i < NH*HD*INTR_D; i += 128) { sWk[i] = Wk[i]; sWv[i] = Wv[i]; }
    for (int i = tid; i < NH*HD;        i += 128) { sbq[i]=bq[i]; sbk[i]=bk[i]; sbv[i]=bv[i]; sva[i]=v_att[i]; }
    for (int i = tid; i < IN_DIM*HID;   i += 128) sW1[i] = W1[i];
    for (int i = tid; i < HID;          i += 128) sb1[i] = b1[i];
    __syncthreads();

    const int warp = tid >> 5, lane = tid & 31;
    const int row  = blockIdx.x * 4 + warp;
    const float T  = fabsf(temperature[0]);

    // stage this row's observation into smem (coalesced per warp)
    const float* orow = obs + (size_t)row * OBS_D;
    for (int i = lane; i < NI*INTR_D; i += 32) sIntr[warp][i] = orow[OWN_D + i];
    if (lane < OWN_D) sOwn[warp][lane] = orow[lane];
    __syncwarp();

    float m[NH], l[NH], cx[NH][HD];

    #pragma unroll
    for (int h = 0; h < NH; h++) {
        // register-hoist this head's weights (q folded with bk)
        float wk[HD][INTR_D], wv[HD][INTR_D], qh[HD], vab[HD], bvr[HD];
        #pragma unroll
        for (int d = 0; d < HD; d++) {
            const int hd = h*HD + d;
            float acc = sbq[hd];
            #pragma unroll
            for (int o = 0; o < OWN_D; o++) acc += sOwn[warp][o] * sWq[hd*OWN_D + o];
            qh[d]  = acc + sbk[hd];          // q + bk (tanh arg bias folded)
            vab[d] = sva[hd];
            bvr[d] = sbv[hd];
            #pragma unroll
            for (int i = 0; i < INTR_D; i++) {
                wk[d][i] = sWk[hd*INTR_D + i];
                wv[d][i] = sWv[hd*INTR_D + i];
            }
        }

        float mh = -1e30f, lh = 0.0f;
        float c0 = 0.f, c1 = 0.f, c2 = 0.f, c3 = 0.f, c4 = 0.f;

        #pragma unroll
        for (int t = 0; t < 8; t++) {
            const int n = (t << 5) + lane;
            const float* p = &sIntr[warp][n*INTR_D];
            const float x0 = p[0], x1 = p[1], x2 = p[2], x3 = p[3], x4 = p[4];
            const float asum = fabsf(x0)+fabsf(x1)+fabsf(x2)+fabsf(x3)+fabsf(x4);

            float sc = 0.0f;
            float vv[HD];
            #pragma unroll
            for (int d = 0; d < HD; d++) {
                float kk = qh[d] + x0*wk[d][0] + x1*wk[d][1] + x2*wk[d][2]
                                 + x3*wk[d][3] + x4*wk[d][4];
                vv[d]    = bvr[d] + x0*wv[d][0] + x1*wv[d][1] + x2*wv[d][2]
                                  + x3*wv[d][3] + x4*wv[d][4];
                sc += fast_tanh(kk) * vab[d];
            }
            sc *= T;
            if (asum < 1e-6f) sc = -1e30f;   // padding mask

            // online softmax update (finite sentinel -> no NaN paths)
            const float mn   = fmaxf(mh, sc);
            const float corr = __expf(mh - mn);
            const float pw   = __expf(sc - mn);
            lh = lh * corr + pw;
            c0 = c0*corr + pw*vv[0];
            c1 = c1*corr + pw*vv[1];
            c2 = c2*corr + pw*vv[2];
            c3 = c3*corr + pw*vv[3];
            c4 = c4*corr + pw*vv[4];
            mh = mn;
        }
        m[h] = mh; l[h] = lh;
        cx[h][0]=c0; cx[h][1]=c1; cx[h][2]=c2; cx[h][3]=c3; cx[h][4]=c4;
    }

    // warp-wide merge of per-lane softmax states
    #pragma unroll
    for (int off = 16; off > 0; off >>= 1) {
        #pragma unroll
        for (int h = 0; h < NH; h++) {
            const float m2 = __shfl_xor_sync(0xffffffffu, m[h], off);
            const float l2 = __shfl_xor_sync(0xffffffffu, l[h], off);
            float c2v[HD];
            #pragma unroll
            for (int d = 0; d < HD; d++) c2v[d] = __shfl_xor_sync(0xffffffffu, cx[h][d], off);
            const float mn = fmaxf(m[h], m2);
            const float a  = __expf(m[h] - mn);
            const float b  = __expf(m2   - mn);
            l[h] = l[h]*a + l2*b;
            #pragma unroll
            for (int d = 0; d < HD; d++) cx[h][d] = cx[h][d]*a + c2v[d]*b;
            m[h] = mn;
        }
    }

    // x = [own, context]
    if (lane < OWN_D) sX[warp][lane] = sOwn[warp][lane];
    if (lane == 0) {
        #pragma unroll
        for (int h = 0; h < NH; h++) {
            // all-padded row => context 0 (matches nan_to_num)
            const float inv = (l[h] > 0.0f && m[h] > -1e29f) ? (1.0f / l[h]) : 0.0f;
            #pragma unroll
            for (int d = 0; d < HD; d++) sX[warp][OWN_D + h*HD + d] = cx[h][d] * inv;
        }
    }
    __syncwarp();

    // layer 1: 22 -> 256, leaky relu, write scratch
    const int rbase = row * HID;
    #pragma unroll
    for (int u = 0; u < 8; u++) {
        const int j = (u << 5) + lane;
        float a = sb1[j];
        #pragma unroll
        for (int i = 0; i < IN_DIM; i++) a += sX[warp][i] * sW1[i*HID + j];
        g_x1[rbase + j] = (a > 0.0f) ? a : 0.2f * a;
    }
}

// ---------------------------------------------------------------------------
// Kernel B: x2 = leaky(x1 @ W2 + b2); out = x2 @ Wf + bf; append log_std.
// 32 rows x 256 cols per CTA, 4x8 register microtile, W2 chunked in smem.
// ---------------------------------------------------------------------------
__global__ void __launch_bounds__(256, 1) mlp2_kernel(
    const float* __restrict__ W2, const float* __restrict__ b2,
    const float* __restrict__ Wf, const float* __restrict__ bf,
    const float* __restrict__ log_std, float* __restrict__ out)
{
    __shared__ float sX1[32][32];        // x1 chunk  (rows x k-chunk)  4 KB
    __shared__ float sW2[32][HID];       // W2 chunk  (k-chunk x cols) 32 KB

    const int tid  = threadIdx.x;
    const int tx   = tid & 31;           // col group: cols tx + 32*j
    const int ty   = tid >> 5;           // row group: rows ty*4 + i
    const int row0 = blockIdx.x * 32;

    float acc[4][8];
    #pragma unroll
    for (int i = 0; i < 4; i++)
        #pragma unroll
        for (int j = 0; j < 8; j++) acc[i][j] = 0.0f;

    for (int kk = 0; kk < HID; kk += 32) {
        __syncthreads();
        // load W2 rows kk..kk+31 (8192 floats) and x1 chunk (1024 floats)
        #pragma unroll
        for (int u = 0; u < 32; u++) {
            const int i = u*256 + tid;
            sW2[i >> 8][i & 255] = W2[kk*HID + i];
        }
        {
            const int i = tid;           // 256 threads cover 1024 in 4 steps
            #pragma unroll
            for (int u = 0; u < 4; u++) {
                const int idx = u*256 + i;
                const int r = idx >> 5, k = idx & 31;
                sX1[r][k] = g_x1[(size_t)(row0 + r)*HID + kk + k];
            }
        }
        __syncthreads();

        #pragma unroll 8
        for (int k = 0; k < 32; k++) {
            float xv[4], wv[8];
            #pragma unroll
            for (int i = 0; i < 4; i++) xv[i] = sX1[ty*4 + i][k];
            #pragma unroll
            for (int j = 0; j < 8; j++) wv[j] = sW2[k][tx + 32*j];
            #pragma unroll
            for (int i = 0; i < 4; i++)
                #pragma unroll
                for (int j = 0; j < 8; j++)
                    acc[i][j] = fmaf(xv[i], wv[j], acc[i][j]);
        }
    }

    // epilogue: bias + leaky + Wf projection, partial per thread
    float po[4][2];
    #pragma unroll
    for (int i = 0; i < 4; i++) { po[i][0] = 0.0f; po[i][1] = 0.0f; }

    #pragma unroll
    for (int j = 0; j < 8; j++) {
        const int c = tx + 32*j;
        const float b2c = b2[c];
        const float wf0 = Wf[c*2 + 0];
        const float wf1 = Wf[c*2 + 1];
        #pragma unroll
        for (int i = 0; i < 4; i++) {
            float v = acc[i][j] + b2c;
            v = (v > 0.0f) ? v : 0.2f * v;
            po[i][0] += v * wf0;
            po[i][1] += v * wf1;
        }
    }

    // reduce across the 32 col-group lanes of this warp
    #pragma unroll
    for (int off = 16; off > 0; off >>= 1) {
        #pragma unroll
        for (int i = 0; i < 4; i++) {
            po[i][0] += __shfl_xor_sync(0xffffffffu, po[i][0], off);
            po[i][1] += __shfl_xor_sync(0xffffffffu, po[i][1], off);
        }
    }

    if (tx == 0) {
        const float ls0 = log_std[0], ls1 = log_std[1];
        const float bf0 = bf[0], bf1 = bf[1];
        #pragma unroll
        for (int i = 0; i < 4; i++) {
            const int r = row0 + ty*4 + i;
            out[r*4 + 0] = po[i][0] + bf0;
            out[r*4 + 1] = po[i][1] + bf1;
            out[r*4 + 2] = ls0;
            out[r*4 + 3] = ls1;
        }
    }
}

// ---------------------------------------------------------------------------
extern "C" void kernel_launch(void* const* d_in, const int* in_sizes, int n_in,
                              void* d_out, int out_size)
{
    const float* obs         = (const float*)d_in[0];
    const float* Wq          = (const float*)d_in[1];
    const float* bq          = (const float*)d_in[2];
    const float* Wk          = (const float*)d_in[3];
    const float* bk          = (const float*)d_in[4];
    const float* Wv          = (const float*)d_in[5];
    const float* bv          = (const float*)d_in[6];
    const float* v_att       = (const float*)d_in[7];
    const float* temperature = (const float*)d_in[8];
    const float* W1          = (const float*)d_in[9];
    const float* b1          = (const float*)d_in[10];
    const float* W2          = (const float*)d_in[11];
    const float* b2          = (const float*)d_in[12];
    const float* Wf          = (const float*)d_in[13];
    const float* bf          = (const float*)d_in[14];
    const float* log_std     = (const float*)d_in[15];
    float* out = (float*)d_out;

    attn_l1_kernel<<<NB/4, 128>>>(obs, Wq, bq, Wk, bk, Wv, bv, v_att,
                                  temperature, W1, b1);
    mlp2_kernel<<<NB/32, 256>>>(W2, b2, Wf, bf, log_std, out);
}

// round 2
// speedup vs baseline: 1.6793x; 1.6793x over previous
#include <cuda_runtime.h>

#define NB      16384
#define OWN_D   7
#define INTR_D  5
#define NH      3
#define HD      5
#define NI      256
#define HID     256
#define IN_DIM  (OWN_D + NH*HD)        // 22
#define OBS_D   (OWN_D + NI*INTR_D)    // 1287

// scratch for x1 = leaky(x @ W1 + b1)
__device__ float g_x1[NB * HID];

// ---------------------------------------------------------------------------
// Kernel A: additive attention + layer 1.  1 warp per batch row, 4 warps/CTA.
//
// Algebra: context_h = bv_h + Wv_h @ (sum_n pw_n x_n) / (sum_n pw_n)
//          score fold: T*sum_d va*tanh(k) = sum_d T*va - sum_d (2T*va)/(1+e^{2k})
//          softmax without running max (scores bounded; shift by T*sum|va|)
// ---------------------------------------------------------------------------
__global__ void __launch_bounds__(128) attn_l1_kernel(
    const float* __restrict__ obs,
    const float* __restrict__ Wq, const float* __restrict__ bq,
    const float* __restrict__ Wk, const float* __restrict__ bk,
    const float* __restrict__ Wv, const float* __restrict__ bv,
    const float* __restrict__ v_att, const float* __restrict__ temperature,
    const float* __restrict__ W1, const float* __restrict__ b1)
{
    __shared__ float sW1[IN_DIM*HID];              // 22.5 KB
    __shared__ float sb1[HID];
    __shared__ float sWq[NH*HD*OWN_D];             // 105
    __shared__ float sWk[NH*HD*INTR_D];            // 75
    __shared__ float sWv[NH*HD*INTR_D];            // 75
    __shared__ float sbq[NH*HD], sbk[NH*HD], sbv[NH*HD], sva[NH*HD];
    __shared__ float sIntr[4][NI*INTR_D];          // 20 KB
    __shared__ float sX[4][IN_DIM];

    const int tid = threadIdx.x;
    for (int i = tid; i < IN_DIM*HID;   i += 128) sW1[i] = W1[i];
    for (int i = tid; i < HID;          i += 128) sb1[i] = b1[i];
    for (int i = tid; i < NH*HD*OWN_D;  i += 128) sWq[i] = Wq[i];
    for (int i = tid; i < NH*HD*INTR_D; i += 128) { sWk[i] = Wk[i]; sWv[i] = Wv[i]; }
    for (int i = tid; i < NH*HD;        i += 128) { sbq[i]=bq[i]; sbk[i]=bk[i]; sbv[i]=bv[i]; sva[i]=v_att[i]; }
    __syncthreads();

    const int warp = tid >> 5, lane = tid & 31;
    const int row  = blockIdx.x * 4 + warp;
    const float T  = fabsf(temperature[0]);

    // stage this row's observation (coalesced per warp)
    const float* orow = obs + (size_t)row * OBS_D;
    float* si = sIntr[warp];
    for (int i = lane; i < NI*INTR_D; i += 32) si[i] = __ldg(orow + OWN_D + i);

    float own[OWN_D];
    #pragma unroll
    for (int o = 0; o < OWN_D; o++) own[o] = __ldg(orow + o);
    __syncwarp();

    constexpr float L2E2 = 2.885390082f;   // 2 * log2(e)
    constexpr float L2E  = 1.442695041f;   // log2(e)

    #pragma unroll
    for (int h = 0; h < NH; h++) {
        // hoist this head's weights (small live set: ~40 floats)
        float wk[HD][INTR_D], qc[HD], va2t[HD];
        float sc0 = 0.0f;                   // sum T*va  -  shift
        #pragma unroll
        for (int d = 0; d < HD; d++) {
            const int hd = h*HD + d;
            float q = sbq[hd] + sbk[hd];
            #pragma unroll
            for (int o = 0; o < OWN_D; o++) q = fmaf(own[o], sWq[hd*OWN_D + o], q);
            qc[d] = q;
            const float vaT = T * sva[hd];
            va2t[d] = 2.0f * vaT;
            sc0 += vaT - fabsf(vaT);        // fold shift = sum |T*va|
            #pragma unroll
            for (int i = 0; i < INTR_D; i++) wk[d][i] = sWk[hd*INTR_D + i];
        }

        float l = 0.0f, s0 = 0.f, s1 = 0.f, s2 = 0.f, s3 = 0.f, s4 = 0.f;

        #pragma unroll
        for (int t = 0; t < 8; t++) {
            const float* p = si + ((t << 5) + lane) * INTR_D;
            const float x0 = p[0], x1 = p[1], x2 = p[2], x3 = p[3], x4 = p[4];
            const float asum = fabsf(x0)+fabsf(x1)+fabsf(x2)+fabsf(x3)+fabsf(x4);

            float sc = sc0;
            #pragma unroll
            for (int d = 0; d < HD; d++) {
                float k = qc[d];
                k = fmaf(x0, wk[d][0], k);
                k = fmaf(x1, wk[d][1], k);
                k = fmaf(x2, wk[d][2], k);
                k = fmaf(x3, wk[d][3], k);
                k = fmaf(x4, wk[d][4], k);
                const float e = exp2f(k * L2E2);              // e^{2k}
                const float r = __fdividef(1.0f, e + 1.0f);   // 1/(1+e^{2k})
                sc = fmaf(-va2t[d], r, sc);                   // += T*va*tanh(k)
            }
            float pw = exp2f(sc * L2E);                       // e^{sc-shift} in [e^-2s, 1]
            if (asum < 1e-6f) pw = 0.0f;                      // padding mask

            l += pw;
            s0 = fmaf(pw, x0, s0);
            s1 = fmaf(pw, x1, s1);
            s2 = fmaf(pw, x2, s2);
            s3 = fmaf(pw, x3, s3);
            s4 = fmaf(pw, x4, s4);
        }

        // warp-sum (plain linear reduction; no max merging needed)
        #pragma unroll
        for (int off = 16; off > 0; off >>= 1) {
            l  += __shfl_xor_sync(0xffffffffu, l,  off);
            s0 += __shfl_xor_sync(0xffffffffu, s0, off);
            s1 += __shfl_xor_sync(0xffffffffu, s1, off);
            s2 += __shfl_xor_sync(0xffffffffu, s2, off);
            s3 += __shfl_xor_sync(0xffffffffu, s3, off);
            s4 += __shfl_xor_sync(0xffffffffu, s4, off);
        }

        if (lane == 0) {
            const float gate = (l > 0.0f) ? 1.0f : 0.0f;      // all-padded -> ctx 0
            const float inv  = (l > 0.0f) ? __fdividef(1.0f, l) : 0.0f;
            const float t0 = s0*inv, t1 = s1*inv, t2 = s2*inv, t3 = s3*inv, t4 = s4*inv;
            #pragma unroll
            for (int d = 0; d < HD; d++) {
                const int hd = h*HD + d;
                float c = sbv[hd];
                c = fmaf(t0, sWv[hd*INTR_D + 0], c);
                c = fmaf(t1, sWv[hd*INTR_D + 1], c);
                c = fmaf(t2, sWv[hd*INTR_D + 2], c);
                c = fmaf(t3, sWv[hd*INTR_D + 3], c);
                c = fmaf(t4, sWv[hd*INTR_D + 4], c);
                sX[warp][OWN_D + hd] = c * gate;
            }
        }
    }

    if (lane < OWN_D) sX[warp][lane] = own[lane];
    __syncwarp();

    // layer 1: 22 -> 256, leaky relu, write scratch
    float xv[IN_DIM];
    #pragma unroll
    for (int i = 0; i < IN_DIM; i++) xv[i] = sX[warp][i];

    const size_t rbase = (size_t)row * HID;
    #pragma unroll
    for (int u = 0; u < 8; u++) {
        const int j = (u << 5) + lane;
        float a = sb1[j];
        #pragma unroll
        for (int i = 0; i < IN_DIM; i++) a = fmaf(xv[i], sW1[i*HID + j], a);
        g_x1[rbase + j] = (a > 0.0f) ? a : 0.2f * a;
    }
}

// ---------------------------------------------------------------------------
// Kernel B: x2 = leaky(x1 @ W2 + b2); out = x2 @ Wf + bf; append log_std.
// (unchanged from R1 — already ~82% of fp32 FFMA roofline)
// ---------------------------------------------------------------------------
__global__ void __launch_bounds__(256, 1) mlp2_kernel(
    const float* __restrict__ W2, const float* __restrict__ b2,
    const float* __restrict__ Wf, const float* __restrict__ bf,
    const float* __restrict__ log_std, float* __restrict__ out)
{
    __shared__ float sX1[32][32];
    __shared__ float sW2[32][HID];

    const int tid  = threadIdx.x;
    const int tx   = tid & 31;
    const int ty   = tid >> 5;
    const int row0 = blockIdx.x * 32;

    float acc[4][8];
    #pragma unroll
    for (int i = 0; i < 4; i++)
        #pragma unroll
        for (int j = 0; j < 8; j++) acc[i][j] = 0.0f;

    for (int kk = 0; kk < HID; kk += 32) {
        __syncthreads();
        #pragma unroll
        for (int u = 0; u < 32; u++) {
            const int i = u*256 + tid;
            sW2[i >> 8][i & 255] = W2[kk*HID + i];
        }
        #pragma unroll
        for (int u = 0; u < 4; u++) {
            const int idx = u*256 + tid;
            const int r = idx >> 5, k = idx & 31;
            sX1[r][k] = g_x1[(size_t)(row0 + r)*HID + kk + k];
        }
        __syncthreads();

        #pragma unroll 8
        for (int k = 0; k < 32; k++) {
            float xv[4], wv[8];
            #pragma unroll
            for (int i = 0; i < 4; i++) xv[i] = sX1[ty*4 + i][k];
            #pragma unroll
            for (int j = 0; j < 8; j++) wv[j] = sW2[k][tx + 32*j];
            #pragma unroll
            for (int i = 0; i < 4; i++)
                #pragma unroll
                for (int j = 0; j < 8; j++)
                    acc[i][j] = fmaf(xv[i], wv[j], acc[i][j]);
        }
    }

    float po[4][2];
    #pragma unroll
    for (int i = 0; i < 4; i++) { po[i][0] = 0.0f; po[i][1] = 0.0f; }

    #pragma unroll
    for (int j = 0; j < 8; j++) {
        const int c = tx + 32*j;
        const float b2c = b2[c];
        const float wf0 = Wf[c*2 + 0];
        const float wf1 = Wf[c*2 + 1];
        #pragma unroll
        for (int i = 0; i < 4; i++) {
            float v = acc[i][j] + b2c;
            v = (v > 0.0f) ? v : 0.2f * v;
            po[i][0] += v * wf0;
            po[i][1] += v * wf1;
        }
    }

    #pragma unroll
    for (int off = 16; off > 0; off >>= 1) {
        #pragma unroll
        for (int i = 0; i < 4; i++) {
            po[i][0] += __shfl_xor_sync(0xffffffffu, po[i][0], off);
            po[i][1] += __shfl_xor_sync(0xffffffffu, po[i][1], off);
        }
    }

    if (tx == 0) {
        const float ls0 = log_std[0], ls1 = log_std[1];
        const float bf0 = bf[0], bf1 = bf[1];
        #pragma unroll
        for (int i = 0; i < 4; i++) {
            const int r = row0 + ty*4 + i;
            out[r*4 + 0] = po[i][0] + bf0;
            out[r*4 + 1] = po[i][1] + bf1;
            out[r*4 + 2] = ls0;
            out[r*4 + 3] = ls1;
        }
    }
}

// ---------------------------------------------------------------------------
extern "C" void kernel_launch(void* const* d_in, const int* in_sizes, int n_in,
                              void* d_out, int out_size)
{
    const float* obs         = (const float*)d_in[0];
    const float* Wq          = (const float*)d_in[1];
    const float* bq          = (const float*)d_in[2];
    const float* Wk          = (const float*)d_in[3];
    const float* bk          = (const float*)d_in[4];
    const float* Wv          = (const float*)d_in[5];
    const float* bv          = (const float*)d_in[6];
    const float* v_att       = (const float*)d_in[7];
    const float* temperature = (const float*)d_in[8];
    const float* W1          = (const float*)d_in[9];
    const float* b1          = (const float*)d_in[10];
    const float* W2          = (const float*)d_in[11];
    const float* b2          = (const float*)d_in[12];
    const float* Wf          = (const float*)d_in[13];
    const float* bf          = (const float*)d_in[14];
    const float* log_std     = (const float*)d_in[15];
    float* out = (float*)d_out;

    attn_l1_kernel<<<NB/4, 128>>>(obs, Wq, bq, Wk, bk, Wv, bv, v_att,
                                  temperature, W1, b1);
    mlp2_kernel<<<NB/32, 256>>>(W2, b2, Wf, bf, log_std, out);
}

// round 3
// speedup vs baseline: 2.4182x; 1.4400x over previous
#include <cuda_runtime.h>

#define NB      16384
#define OWN_D   7
#define INTR_D  5
#define NH      3
#define HD      5
#define NI      256
#define HID     256
#define IN_DIM  (OWN_D + NH*HD)        // 22
#define OBS_D   (OWN_D + NI*INTR_D)    // 1287

// attention output x = [own, context]  (1.4 MB scratch)
__device__ float g_x[NB * IN_DIM];

typedef unsigned long long ull;

__device__ __forceinline__ ull pack2(float lo, float hi) {
    ull r; asm("mov.b64 %0, {%1, %2};" : "=l"(r) : "f"(lo), "f"(hi)); return r;
}
__device__ __forceinline__ void unpack2(ull v, float& lo, float& hi) {
    asm("mov.b64 {%0, %1}, %2;" : "=f"(lo), "=f"(hi) : "l"(v));
}
__device__ __forceinline__ void fma2(ull& d, ull a, ull b) {
    asm("fma.rn.f32x2 %0, %1, %2, %0;" : "+l"(d) : "l"(a), "l"(b));
}

// ---------------------------------------------------------------------------
// Kernel A: additive attention only.  1 warp per row, 4 warps/CTA, ~1.5KB smem
// -> 4 CTAs/SM, 4 warps/SMSP.  Items held in registers across the head loop.
// ---------------------------------------------------------------------------
__global__ void __launch_bounds__(128, 4) attn_kernel(
    const float* __restrict__ obs,
    const float* __restrict__ Wq, const float* __restrict__ bq,
    const float* __restrict__ Wk, const float* __restrict__ bk,
    const float* __restrict__ Wv, const float* __restrict__ bv,
    const float* __restrict__ v_att, const float* __restrict__ temperature)
{
    __shared__ float sWq[NH*HD*OWN_D];             // 105
    __shared__ float sWk[NH*HD*INTR_D];            // 75
    __shared__ float sWv[NH*HD*INTR_D];            // 75
    __shared__ float sbq[NH*HD], sbk[NH*HD], sbv[NH*HD], sva[NH*HD];

    const int tid = threadIdx.x;
    for (int i = tid; i < NH*HD*OWN_D;  i += 128) sWq[i] = Wq[i];
    for (int i = tid; i < NH*HD*INTR_D; i += 128) { sWk[i] = Wk[i]; sWv[i] = Wv[i]; }
    for (int i = tid; i < NH*HD;        i += 128) { sbq[i]=bq[i]; sbk[i]=bk[i]; sbv[i]=bv[i]; sva[i]=v_att[i]; }
    __syncthreads();

    const int warp = tid >> 5, lane = tid & 31;
    const int row  = blockIdx.x * 4 + warp;
    const float T  = fabsf(temperature[0]);
    const float* orow = obs + (size_t)row * OBS_D;

    float own[OWN_D];
    #pragma unroll
    for (int o = 0; o < OWN_D; o++) own[o] = __ldg(orow + o);

    // this lane's 8 items, in registers
    float it[8][INTR_D];
    #pragma unroll
    for (int t = 0; t < 8; t++) {
        const float* p = orow + OWN_D + ((t << 5) + lane) * INTR_D;
        #pragma unroll
        for (int i = 0; i < INTR_D; i++) it[t][i] = __ldg(p + i);
    }
    float asum[8];
    #pragma unroll
    for (int t = 0; t < 8; t++)
        asum[t] = fabsf(it[t][0])+fabsf(it[t][1])+fabsf(it[t][2])
                 +fabsf(it[t][3])+fabsf(it[t][4]);

    constexpr float L2E2 = 2.885390082f;   // 2*log2(e)
    constexpr float L2E  = 1.442695041f;   // log2(e)

    #pragma unroll
    for (int h = 0; h < NH; h++) {
        float wk[HD][INTR_D], qc[HD], va2t[HD];
        float sc0 = 0.0f;
        #pragma unroll
        for (int d = 0; d < HD; d++) {
            const int hd = h*HD + d;
            float q = sbq[hd] + sbk[hd];
            #pragma unroll
            for (int o = 0; o < OWN_D; o++) q = fmaf(own[o], sWq[hd*OWN_D + o], q);
            qc[d] = q;
            const float vaT = T * sva[hd];
            va2t[d] = 2.0f * vaT;
            sc0 += vaT - fabsf(vaT);       // fold shift = sum|T*va|
            #pragma unroll
            for (int i = 0; i < INTR_D; i++) wk[d][i] = sWk[hd*INTR_D + i];
        }

        float l = 0.0f, s0 = 0.f, s1 = 0.f, s2 = 0.f, s3 = 0.f, s4 = 0.f;

        #pragma unroll
        for (int t = 0; t < 8; t++) {
            const float x0 = it[t][0], x1 = it[t][1], x2 = it[t][2],
                        x3 = it[t][3], x4 = it[t][4];
            float sc = sc0;
            #pragma unroll
            for (int d = 0; d < HD; d++) {
                float k = qc[d];
                k = fmaf(x0, wk[d][0], k);
                k = fmaf(x1, wk[d][1], k);
                k = fmaf(x2, wk[d][2], k);
                k = fmaf(x3, wk[d][3], k);
                k = fmaf(x4, wk[d][4], k);
                const float e = exp2f(k * L2E2);
                const float r = __fdividef(1.0f, e + 1.0f);
                sc = fmaf(-va2t[d], r, sc);
            }
            float pw = exp2f(sc * L2E);
            if (asum[t] < 1e-6f) pw = 0.0f;

            l += pw;
            s0 = fmaf(pw, x0, s0);
            s1 = fmaf(pw, x1, s1);
            s2 = fmaf(pw, x2, s2);
            s3 = fmaf(pw, x3, s3);
            s4 = fmaf(pw, x4, s4);
        }

        #pragma unroll
        for (int off = 16; off > 0; off >>= 1) {
            l  += __shfl_xor_sync(0xffffffffu, l,  off);
            s0 += __shfl_xor_sync(0xffffffffu, s0, off);
            s1 += __shfl_xor_sync(0xffffffffu, s1, off);
            s2 += __shfl_xor_sync(0xffffffffu, s2, off);
            s3 += __shfl_xor_sync(0xffffffffu, s3, off);
            s4 += __shfl_xor_sync(0xffffffffu, s4, off);
        }

        if (lane == 0) {
            const float gate = (l > 0.0f) ? 1.0f : 0.0f;
            const float inv  = (l > 0.0f) ? __fdividef(1.0f, l) : 0.0f;
            const float t0 = s0*inv, t1 = s1*inv, t2 = s2*inv, t3 = s3*inv, t4 = s4*inv;
            #pragma unroll
            for (int d = 0; d < HD; d++) {
                const int hd = h*HD + d;
                float c = sbv[hd];
                c = fmaf(t0, sWv[hd*INTR_D + 0], c);
                c = fmaf(t1, sWv[hd*INTR_D + 1], c);
                c = fmaf(t2, sWv[hd*INTR_D + 2], c);
                c = fmaf(t3, sWv[hd*INTR_D + 3], c);
                c = fmaf(t4, sWv[hd*INTR_D + 4], c);
                g_x[(size_t)row*IN_DIM + OWN_D + hd] = c * gate;
            }
        }
    }

    if (lane < OWN_D) g_x[(size_t)row*IN_DIM + lane] = __ldg(orow + lane);
}

// ---------------------------------------------------------------------------
// Kernel B: x1 = leaky(x@W1+b1) per k-chunk; x2 = leaky(x1@W2+b2);
//           out = x2@Wf + bf; append log_std.
// 64 rows x 256 cols per CTA, 8x8 microtile as packed f32x2 (FFMA2).
// ---------------------------------------------------------------------------
__global__ void __launch_bounds__(256, 2) mlp_kernel(
    const float* __restrict__ W1, const float* __restrict__ b1,
    const float* __restrict__ W2, const float* __restrict__ b2,
    const float* __restrict__ Wf, const float* __restrict__ bf,
    const float* __restrict__ log_std, float* __restrict__ out)
{
    __shared__ alignas(16) float sW2k[32*256];   // 32 KB  [k][c]
    __shared__ float sX1k[32*66];                // 8.25KB [k][row], pad 66
    __shared__ float sX[64*IN_DIM];              // 5.5 KB [row][22]

    const int tid  = threadIdx.x;
    const int tx   = tid & 31;            // col group: cols tx*8 .. tx*8+7
    const int ty   = tid >> 5;            // row group: rows ty*8 .. ty*8+7
    const int c0   = tx * 8;
    const int r0   = ty * 8;
    const int row0 = blockIdx.x * 64;

    for (int idx = tid; idx < 64*IN_DIM; idx += 256)
        sX[idx] = g_x[(size_t)row0*IN_DIM + idx];
    __syncthreads();

    ull acc[4][8];
    #pragma unroll
    for (int p = 0; p < 4; p++)
        #pragma unroll
        for (int j = 0; j < 8; j++) acc[p][j] = 0ULL;

    for (int ch = 0; ch < 8; ch++) {
        const int kk = ch * 32;

        // stage W2 chunk [32][256]
        {
            const float4* src = (const float4*)(W2 + (size_t)kk * HID);
            float4* dst = (float4*)sW2k;
            #pragma unroll
            for (int u = 0; u < 8; u++) dst[u*256 + tid] = src[u*256 + tid];
        }

        // compute x1 chunk: this thread owns column kk+tx, rows r0..r0+7
        {
            float wcol[IN_DIM];
            #pragma unroll
            for (int i = 0; i < IN_DIM; i++) wcol[i] = __ldg(W1 + i*HID + kk + tx);
            const float bb = __ldg(b1 + kk + tx);
            float a[8];
            #pragma unroll
            for (int j = 0; j < 8; j++) a[j] = bb;
            #pragma unroll
            for (int i = 0; i < IN_DIM; i++) {
                #pragma unroll
                for (int j = 0; j < 8; j++)
                    a[j] = fmaf(sX[(r0 + j)*IN_DIM + i], wcol[i], a[j]);
            }
            #pragma unroll
            for (int j = 0; j < 8; j++) {
                const float v = a[j];
                sX1k[tx*66 + r0 + j] = (v > 0.0f) ? v : 0.2f * v;
            }
        }
        __syncthreads();

        #pragma unroll 8
        for (int k = 0; k < 32; k++) {
            ull xv[4];
            #pragma unroll
            for (int p = 0; p < 4; p++)
                xv[p] = *(const ull*)&sX1k[k*66 + r0 + 2*p];
            const float4 w0 = *(const float4*)&sW2k[k*256 + c0];
            const float4 w1 = *(const float4*)&sW2k[k*256 + c0 + 4];
            ull wd[8];
            wd[0] = pack2(w0.x, w0.x); wd[1] = pack2(w0.y, w0.y);
            wd[2] = pack2(w0.z, w0.z); wd[3] = pack2(w0.w, w0.w);
            wd[4] = pack2(w1.x, w1.x); wd[5] = pack2(w1.y, w1.y);
            wd[6] = pack2(w1.z, w1.z); wd[7] = pack2(w1.w, w1.w);
            #pragma unroll
            for (int p = 0; p < 4; p++)
                #pragma unroll
                for (int j = 0; j < 8; j++)
                    fma2(acc[p][j], xv[p], wd[j]);
        }
        __syncthreads();
    }

    // epilogue: bias + leaky + Wf projection
    float b2r[8], wf0[8], wf1[8];
    {
        const float4 ba = *(const float4*)&b2[c0];
        const float4 bb = *(const float4*)&b2[c0 + 4];
        b2r[0]=ba.x; b2r[1]=ba.y; b2r[2]=ba.z; b2r[3]=ba.w;
        b2r[4]=bb.x; b2r[5]=bb.y; b2r[6]=bb.z; b2r[7]=bb.w;
        #pragma unroll
        for (int u = 0; u < 4; u++) {
            const float4 w = *(const float4*)&Wf[c0*2 + u*4];
            wf0[u*2+0] = w.x; wf1[u*2+0] = w.y;
            wf0[u*2+1] = w.z; wf1[u*2+1] = w.w;
        }
    }

    float po0[8], po1[8];
    #pragma unroll
    for (int i = 0; i < 8; i++) { po0[i] = 0.0f; po1[i] = 0.0f; }

    #pragma unroll
    for (int p = 0; p < 4; p++) {
        #pragma unroll
        for (int j = 0; j < 8; j++) {
            float vl, vh;
            unpack2(acc[p][j], vl, vh);
            vl += b2r[j]; vl = (vl > 0.0f) ? vl : 0.2f * vl;
            vh += b2r[j]; vh = (vh > 0.0f) ? vh : 0.2f * vh;
            po0[2*p  ] = fmaf(vl, wf0[j], po0[2*p  ]);
            po1[2*p  ] = fmaf(vl, wf1[j], po1[2*p  ]);
            po0[2*p+1] = fmaf(vh, wf0[j], po0[2*p+1]);
            po1[2*p+1] = fmaf(vh, wf1[j], po1[2*p+1]);
        }
    }

    #pragma unroll
    for (int off = 16; off > 0; off >>= 1) {
        #pragma unroll
        for (int i = 0; i < 8; i++) {
            po0[i] += __shfl_xor_sync(0xffffffffu, po0[i], off);
            po1[i] += __shfl_xor_sync(0xffffffffu, po1[i], off);
        }
    }

    if (tx == 0) {
        const float bf0 = bf[0], bf1 = bf[1];
        const float ls0 = log_std[0], ls1 = log_std[1];
        #pragma unroll
        for (int i = 0; i < 8; i++) {
            const int r = row0 + r0 + i;
            float4 o;
            o.x = po0[i] + bf0;
            o.y = po1[i] + bf1;
            o.z = ls0;
            o.w = ls1;
            *(float4*)&out[(size_t)r*4] = o;
        }
    }
}

// ---------------------------------------------------------------------------
extern "C" void kernel_launch(void* const* d_in, const int* in_sizes, int n_in,
                              void* d_out, int out_size)
{
    const float* obs         = (const float*)d_in[0];
    const float* Wq          = (const float*)d_in[1];
    const float* bq          = (const float*)d_in[2];
    const float* Wk          = (const float*)d_in[3];
    const float* bk          = (const float*)d_in[4];
    const float* Wv          = (const float*)d_in[5];
    const float* bv          = (const float*)d_in[6];
    const float* v_att       = (const float*)d_in[7];
    const float* temperature = (const float*)d_in[8];
    const float* W1          = (const float*)d_in[9];
    const float* b1          = (const float*)d_in[10];
    const float* W2          = (const float*)d_in[11];
    const float* b2          = (const float*)d_in[12];
    const float* Wf          = (const float*)d_in[13];
    const float* bf          = (const float*)d_in[14];
    const float* log_std     = (const float*)d_in[15];
    float* out = (float*)d_out;

    attn_kernel<<<NB/4, 128>>>(obs, Wq, bq, Wk, bk, Wv, bv, v_att, temperature);
    mlp_kernel<<<NB/64, 256>>>(W1, b1, W2, b2, Wf, bf, log_std, out);
}